// round 4
// baseline (speedup 1.0000x reference)
#include <cuda_runtime.h>
#include <math.h>

#define BROWS 256
#define FDIM  256
#define HDIM  1024
#define NX    (BROWS*FDIM)
#define NB    148
#define NT    256

// ---------------- persistent device state (no allocations) ----------------
__device__ float g_xbuf[2][NX];          // ping-pong x / x5
__device__ float g_h [BROWS*HDIM];       // hidden activations
__device__ float g_k [7][NX];            // RK stage derivatives
__device__ float g_part[NB];             // per-block error partials
__device__ float g_t, g_dt;
__device__ int   g_par;
__device__ unsigned g_bar;               // cumulative grid-barrier counter

// ---------------- Dormand-Prince tableau ----------------------------------
__constant__ float c_A[7][6] = {
  {0,0,0,0,0,0},
  {(float)(1.0/5.0),0,0,0,0,0},
  {(float)(3.0/40.0),(float)(9.0/40.0),0,0,0,0},
  {(float)(44.0/45.0),(float)(-56.0/15.0),(float)(32.0/9.0),0,0,0},
  {(float)(19372.0/6561.0),(float)(-25360.0/2187.0),(float)(64448.0/6561.0),(float)(-212.0/729.0),0,0},
  {(float)(9017.0/3168.0),(float)(-355.0/33.0),(float)(46732.0/5247.0),(float)(49.0/176.0),(float)(-5103.0/18656.0),0},
  {(float)(35.0/384.0),0.0f,(float)(500.0/1113.0),(float)(125.0/192.0),(float)(-2187.0/6784.0),(float)(11.0/84.0)},
};
__constant__ float c_C[7]  = {0.f,0.2f,0.3f,0.8f,(float)(8.0/9.0),1.f,1.f};
__constant__ float c_B5[7] = {(float)(35.0/384.0),0.f,(float)(500.0/1113.0),(float)(125.0/192.0),
                              (float)(-2187.0/6784.0),(float)(11.0/84.0),0.f};
__constant__ float c_D[7]  = {
  (float)(35.0/384.0 - 5179.0/57600.0),
  0.f,
  (float)(500.0/1113.0 - 7571.0/16695.0),
  (float)(125.0/192.0 - 393.0/640.0),
  (float)(-2187.0/6784.0 + 92097.0/339200.0),
  (float)(11.0/84.0 - 187.0/2100.0),
  (float)(-1.0/40.0)};

// ---------------- init: reset state every graph replay ---------------------
__global__ void k_init(const float* __restrict__ x0, float* __restrict__ out) {
  int i = blockIdx.x*blockDim.x + threadIdx.x;
  if (i < NX) { g_xbuf[0][i] = x0[i]; out[i] = x0[i]; }
  if (i == 0) { g_t = 0.f; g_dt = 0.05f; g_par = 0; g_bar = 0u; }
}

// ---------------- software grid barrier ------------------------------------
// Cumulative-counter barrier: release via __threadfence + atomicAdd, wait via
// ld.acquire.gpu spin. The trailing __threadfence() (gpu scope) emits
// CCTL.IVALL on sm_103a, invalidating L1D so post-barrier loads of other
// blocks' writes hit L2 instead of stale L1 lines.
__device__ __forceinline__ void gridbar() {
  __syncthreads();
  if (threadIdx.x == 0) {
    __threadfence();
    unsigned gen = atomicAdd(&g_bar, 1u);
    unsigned target = gen - (gen % NB) + NB;
    unsigned v;
    do {
      asm volatile("ld.acquire.gpu.u32 %0, [%1];" : "=r"(v) : "l"(&g_bar) : "memory");
    } while ((int)(v - target) < 0);
    __threadfence();
  }
  __syncthreads();
}

// ---------------- GEMM1: h = tanh(xi @ W1[:-1] + ts*W1[-1] + b1) -----------
// 128 jobs: 8 row-tiles (32) x 16 col-tiles (64). xi built on the fly.
__device__ __forceinline__ void gemm1(const float* __restrict__ cur,
    const float* __restrict__ W1, const float* __restrict__ b1,
    int s, float ts, const float* ca, float* shA, float* shB, int b)
{
  const int tid = threadIdx.x;
  const int tx = tid & 15, ty = tid >> 4;
  const int bm = (b >> 4) * 32;
  const int bn = (b & 15) * 64;
  const int lm = tid >> 4, lk = tid & 15;   // A-tile load map (32x16)
  const int bk = tid >> 6, bnn = tid & 63;  // B-tile load map (16x64)
  float acc[2][4] = {{0,0,0,0},{0,0,0,0}};

  for (int k0 = 0; k0 < FDIM; k0 += 16) {
    #pragma unroll
    for (int rr = 0; rr < 2; rr++) {
      int row = lm + rr*16;
      int gi  = (bm + row)*FDIM + k0 + lk;
      float v = cur[gi];
      for (int j = 0; j < s; j++) v = fmaf(ca[j], g_k[j][gi], v);
      shA[row*17 + lk] = v;
    }
    #pragma unroll
    for (int rr = 0; rr < 4; rr++)
      shB[(bk + rr*4)*64 + bnn] = W1[(k0 + bk + rr*4)*HDIM + bn + bnn];
    __syncthreads();
    #pragma unroll
    for (int kk = 0; kk < 16; kk++) {
      float a0 = shA[(ty*2 + 0)*17 + kk];
      float a1 = shA[(ty*2 + 1)*17 + kk];
      float4 bb = *(const float4*)&shB[kk*64 + tx*4];
      acc[0][0] = fmaf(a0, bb.x, acc[0][0]);
      acc[0][1] = fmaf(a0, bb.y, acc[0][1]);
      acc[0][2] = fmaf(a0, bb.z, acc[0][2]);
      acc[0][3] = fmaf(a0, bb.w, acc[0][3]);
      acc[1][0] = fmaf(a1, bb.x, acc[1][0]);
      acc[1][1] = fmaf(a1, bb.y, acc[1][1]);
      acc[1][2] = fmaf(a1, bb.z, acc[1][2]);
      acc[1][3] = fmaf(a1, bb.w, acc[1][3]);
    }
    __syncthreads();
  }
  int n = bn + tx*4;
  float4 wt = *(const float4*)&W1[FDIM*HDIM + n];
  float4 b4 = *(const float4*)&b1[n];
  #pragma unroll
  for (int rr = 0; rr < 2; rr++) {
    int row = bm + ty*2 + rr;
    float4 o;
    o.x = tanhf(fmaf(ts, wt.x, acc[rr][0] + b4.x));
    o.y = tanhf(fmaf(ts, wt.y, acc[rr][1] + b4.y));
    o.z = tanhf(fmaf(ts, wt.z, acc[rr][2] + b4.z));
    o.w = tanhf(fmaf(ts, wt.w, acc[rr][3] + b4.w));
    *(float4*)&g_h[row*HDIM + n] = o;
  }
}

// ---------------- GEMM2: k_s = h @ W2 + b2 ---------------------------------
// 128 jobs: 16 row-tiles (16) x 8 col-tiles (32), full K=1024.
__device__ __forceinline__ void gemm2(const float* __restrict__ W2,
    const float* __restrict__ b2, int s, float* shA, float* shB, int b)
{
  const int tid = threadIdx.x;
  const int tx = tid & 15, ty = tid >> 4;
  const int bm = (b >> 3) * 16;
  const int bn = (b & 7) * 32;
  const int lm = tid >> 5, lk = tid & 31;
  float ax = 0.f, ay = 0.f;

  for (int k0 = 0; k0 < HDIM; k0 += 32) {
    #pragma unroll
    for (int rr = 0; rr < 2; rr++)
      shA[(lm + rr*8)*33 + lk] = g_h[(bm + lm + rr*8)*HDIM + k0 + lk];
    #pragma unroll
    for (int rr = 0; rr < 4; rr++)
      shB[(lm + rr*8)*34 + lk] = W2[(k0 + lm + rr*8)*FDIM + bn + lk];
    __syncthreads();
    #pragma unroll
    for (int kk = 0; kk < 32; kk++) {
      float a = shA[ty*33 + kk];
      float2 bb = *(const float2*)&shB[kk*34 + tx*2];
      ax = fmaf(a, bb.x, ax);
      ay = fmaf(a, bb.y, ay);
    }
    __syncthreads();
  }
  int n = bn + tx*2;
  float2 o; o.x = ax + b2[n]; o.y = ay + b2[n+1];
  *(float2*)&g_k[s][(bm + ty)*FDIM + n] = o;
}

// ---------------- persistent solver kernel ---------------------------------
__global__ void __launch_bounds__(NT, 1) k_ode(
    const float* __restrict__ W1, const float* __restrict__ b1,
    const float* __restrict__ W2, const float* __restrict__ b2,
    float* __restrict__ out)
{
  __shared__ float shA[560];
  __shared__ float shB[1100];
  const int b = blockIdx.x, tid = threadIdx.x;

  for (int it = 0; it < 64; it++) {
    float t = *(volatile float*)&g_t;
    if (t >= 1.0f) break;                         // uniform across the grid
    float dt  = *(volatile float*)&g_dt;
    int   par = *(volatile int*)&g_par;
    const float* cur = g_xbuf[par];
    float*       nxt = g_xbuf[par ^ 1];
    float dt_c = fmaxf(fminf(dt, 1.0f - t), 0.0f);

    for (int s = 0; s < 7; s++) {
      if (b < 128) {
        float ts = t + c_C[s]*dt_c;
        float ca[6];
        #pragma unroll
        for (int j = 0; j < 6; j++) ca[j] = dt_c * c_A[s][j];
        gemm1(cur, W1, b1, s, ts, ca, shA, shB, b);
      }
      gridbar();
      if (b < 128) gemm2(W2, b2, s, shA, shB, b);
      gridbar();
    }

    // x5, err, per-block partial
    {
      float cb[7], cd[7];
      #pragma unroll
      for (int j = 0; j < 7; j++) { cb[j] = dt_c*c_B5[j]; cd[j] = dt_c*c_D[j]; }
      float local = 0.f;
      for (int i = b*NT + tid; i < NX; i += NB*NT) {
        float x = cur[i], x5 = x, err = 0.f;
        #pragma unroll
        for (int j = 0; j < 7; j++) {
          float kv = g_k[j][i];
          x5  = fmaf(cb[j], kv, x5);
          err = fmaf(cd[j], kv, err);
        }
        nxt[i] = x5;
        float scale = fmaf(1e-3f, fmaxf(fabsf(x), fabsf(x5)), 1e-4f);
        float r = err / scale;
        local = fmaf(r, r, local);
      }
      shA[tid] = local;
      __syncthreads();
      #pragma unroll
      for (int st = 128; st > 0; st >>= 1) {
        if (tid < st) shA[tid] += shA[tid + st];
        __syncthreads();
      }
      if (tid == 0) g_part[b] = shA[0];
    }
    gridbar();

    // finalize scalars (block 0)
    if (b == 0) {
      float v = (tid < NB) ? g_part[tid] : 0.f;
      shA[tid] = v;
      __syncthreads();
      #pragma unroll
      for (int st = 128; st > 0; st >>= 1) {
        if (tid < st) shA[tid] += shA[tid + st];
        __syncthreads();
      }
      if (tid == 0) {
        float err_norm = sqrtf(shA[0] * (1.0f/(float)NX));
        int accept = (err_norm <= 1.0f);
        float factor = 0.9f * powf(err_norm + 1e-10f, -0.2f);
        factor = fminf(fmaxf(factor, 0.2f), 5.0f);
        if (accept) { g_t = t + dt_c; g_par = par ^ 1; }
        g_dt = dt_c * factor;
      }
    }
    gridbar();
  }

  // write final trajectory row
  {
    int par = *(volatile int*)&g_par;
    const float* xf = g_xbuf[par];
    for (int i = b*NT + tid; i < NX; i += NB*NT) out[NX + i] = xf[i];
  }
}

extern "C" void kernel_launch(void* const* d_in, const int* in_sizes, int n_in,
                              void* d_out, int out_size) {
  const float* x0 = (const float*)d_in[0];
  const float* W1 = (const float*)d_in[1];
  const float* b1 = (const float*)d_in[2];
  const float* W2 = (const float*)d_in[3];
  const float* b2 = (const float*)d_in[4];
  float* out = (float*)d_out;

  k_init<<<256, 256>>>(x0, out);
  k_ode<<<NB, NT>>>(W1, b1, W2, b2, out);
}

// round 5
// speedup vs baseline: 1.8064x; 1.8064x over previous
#include <cuda_runtime.h>
#include <math.h>

#define BROWS 256
#define FDIM  256
#define HDIM  1024
#define NX    (BROWS*FDIM)
#define NB    128
#define NT    512

// ---------------- persistent device state (no allocations) ----------------
__device__ float g_xbuf[2][NX];          // ping-pong x / x5
__device__ float g_h [BROWS*HDIM];       // hidden activations
__device__ float g_k [8][NX];            // RK stage ring (8 slots for FSAL rotation)
__device__ float g_part[NB];             // per-block error partials
__device__ float g_t, g_dt;
__device__ int   g_par, g_kbase, g_fsal;
__device__ unsigned g_bar;               // cumulative grid-barrier counter

// ---------------- Dormand-Prince tableau ----------------------------------
__constant__ float c_A[7][6] = {
  {0,0,0,0,0,0},
  {(float)(1.0/5.0),0,0,0,0,0},
  {(float)(3.0/40.0),(float)(9.0/40.0),0,0,0,0},
  {(float)(44.0/45.0),(float)(-56.0/15.0),(float)(32.0/9.0),0,0,0},
  {(float)(19372.0/6561.0),(float)(-25360.0/2187.0),(float)(64448.0/6561.0),(float)(-212.0/729.0),0,0},
  {(float)(9017.0/3168.0),(float)(-355.0/33.0),(float)(46732.0/5247.0),(float)(49.0/176.0),(float)(-5103.0/18656.0),0},
  {(float)(35.0/384.0),0.0f,(float)(500.0/1113.0),(float)(125.0/192.0),(float)(-2187.0/6784.0),(float)(11.0/84.0)},
};
__constant__ float c_C[7]  = {0.f,0.2f,0.3f,0.8f,(float)(8.0/9.0),1.f,1.f};
__constant__ float c_B5[7] = {(float)(35.0/384.0),0.f,(float)(500.0/1113.0),(float)(125.0/192.0),
                              (float)(-2187.0/6784.0),(float)(11.0/84.0),0.f};
__constant__ float c_D[7]  = {
  (float)(35.0/384.0 - 5179.0/57600.0),
  0.f,
  (float)(500.0/1113.0 - 7571.0/16695.0),
  (float)(125.0/192.0 - 393.0/640.0),
  (float)(-2187.0/6784.0 + 92097.0/339200.0),
  (float)(11.0/84.0 - 187.0/2100.0),
  (float)(-1.0/40.0)};

// ---------------- shared-memory layout (floats) ----------------------------
#define SM_W1    0          // [256][64]  GEMM1 weight slice
#define SM_W2    16384      // [1024][16] GEMM2 weight slice
#define SM_W1T   32768      // [64]  time row of W1
#define SM_B1    32832      // [64]  b1 slice
#define SM_B2    32896      // [16]  b2 slice
#define SM_SCR   32912      // [8320] scratch: A slabs / reductions
#define SM_FLOATS (SM_SCR + 8320)
#define SMEM_BYTES (SM_FLOATS * 4)

// ---------------- init: reset state every graph replay ---------------------
__global__ void k_init(const float* __restrict__ x0, float* __restrict__ out) {
  int i = blockIdx.x*blockDim.x + threadIdx.x;
  if (i < NX) { g_xbuf[0][i] = x0[i]; out[i] = x0[i]; }
  if (i == 0) { g_t = 0.f; g_dt = 0.05f; g_par = 0; g_kbase = 0; g_fsal = 0; g_bar = 0u; }
}

// ---------------- software grid barrier ------------------------------------
__device__ __forceinline__ void gridbar() {
  __syncthreads();
  if (threadIdx.x == 0) {
    __threadfence();
    unsigned gen = atomicAdd(&g_bar, 1u);
    unsigned target = gen - (gen % NB) + NB;
    unsigned v;
    do {
      asm volatile("ld.acquire.gpu.u32 %0, [%1];" : "=r"(v) : "l"(&g_bar) : "memory");
    } while ((int)(v - target) < 0);
    __threadfence();
  }
  __syncthreads();
}

// ---------------- persistent solver kernel ---------------------------------
__global__ void __launch_bounds__(NT, 1) k_ode(
    const float* __restrict__ W1, const float* __restrict__ b1,
    const float* __restrict__ W2, const float* __restrict__ b2,
    float* __restrict__ out)
{
  extern __shared__ float sm[];
  const int b = blockIdx.x, tid = threadIdx.x;

  const int bRm = (b >> 4) * 32;     // 32-row slab (both GEMMs)
  const int bHn = (b & 15) * 64;     // GEMM1 h-column slice (64)
  const int bKn = (b & 15) * 16;     // GEMM2 k-column slice (16)

  // ---- prologue: stage weight slices into smem (persist across all iters) --
  for (int i = tid; i < 256*64; i += NT)
    sm[SM_W1 + i] = W1[(i >> 6)*HDIM + bHn + (i & 63)];
  for (int i = tid; i < 1024*16; i += NT)
    sm[SM_W2 + i] = W2[(i >> 4)*FDIM + bKn + (i & 15)];
  if (tid < 64) {
    sm[SM_W1T + tid] = W1[FDIM*HDIM + bHn + tid];
    sm[SM_B1  + tid] = b1[bHn + tid];
  }
  if (tid < 16) sm[SM_B2 + tid] = b2[bKn + tid];
  __syncthreads();

  float* sA = &sm[SM_SCR];

  for (int it = 0; it < 64; it++) {
    float t = *(volatile float*)&g_t;
    if (t >= 1.0f) break;                         // uniform across the grid
    float dt    = *(volatile float*)&g_dt;
    int   par   = *(volatile int*)&g_par;
    int   kbase = *(volatile int*)&g_kbase;
    int   fsal  = *(volatile int*)&g_fsal;
    const float* cur = g_xbuf[par];
    float*       nxt = g_xbuf[par ^ 1];
    float dt_c = fmaxf(fminf(dt, 1.0f - t), 0.0f);

    for (int s = fsal ? 1 : 0; s < 7; s++) {
      // ---- GEMM1: h = tanh(xi @ W1[:-1] + ts*W1[-1] + b1), tile 32x64 ----
      {
        float ts = t + c_C[s]*dt_c;
        float ca[6];
        #pragma unroll
        for (int j = 0; j < 6; j++) ca[j] = dt_c * c_A[s][j];

        // build xi slab [32][260] (k-contig, padded for float4)
        for (int i = tid; i < 32*256; i += NT) {
          int m = i >> 8, kk = i & 255;
          int gi = (bRm + m)*FDIM + kk;
          float v = cur[gi];
          for (int j = 0; j < s; j++) v = fmaf(ca[j], g_k[(kbase + j) & 7][gi], v);
          sA[m*260 + kk] = v;
        }
        __syncthreads();

        const int n = tid & 63, mg = tid >> 6;   // 4 rows x 1 col per thread
        const float* a0p = &sA[(mg*4 + 0)*260];
        const float* a1p = &sA[(mg*4 + 1)*260];
        const float* a2p = &sA[(mg*4 + 2)*260];
        const float* a3p = &sA[(mg*4 + 3)*260];
        float acc0 = 0.f, acc1 = 0.f, acc2 = 0.f, acc3 = 0.f;
        #pragma unroll 4
        for (int k = 0; k < 256; k += 4) {
          float4 a0 = *(const float4*)(a0p + k);
          float4 a1 = *(const float4*)(a1p + k);
          float4 a2 = *(const float4*)(a2p + k);
          float4 a3 = *(const float4*)(a3p + k);
          float b0 = sm[SM_W1 + (k+0)*64 + n];
          float b1v= sm[SM_W1 + (k+1)*64 + n];
          float b2v= sm[SM_W1 + (k+2)*64 + n];
          float b3 = sm[SM_W1 + (k+3)*64 + n];
          acc0 = fmaf(a0.x,b0,acc0); acc0 = fmaf(a0.y,b1v,acc0);
          acc0 = fmaf(a0.z,b2v,acc0); acc0 = fmaf(a0.w,b3,acc0);
          acc1 = fmaf(a1.x,b0,acc1); acc1 = fmaf(a1.y,b1v,acc1);
          acc1 = fmaf(a1.z,b2v,acc1); acc1 = fmaf(a1.w,b3,acc1);
          acc2 = fmaf(a2.x,b0,acc2); acc2 = fmaf(a2.y,b1v,acc2);
          acc2 = fmaf(a2.z,b2v,acc2); acc2 = fmaf(a2.w,b3,acc2);
          acc3 = fmaf(a3.x,b0,acc3); acc3 = fmaf(a3.y,b1v,acc3);
          acc3 = fmaf(a3.z,b2v,acc3); acc3 = fmaf(a3.w,b3,acc3);
        }
        float wt = sm[SM_W1T + n], bb = sm[SM_B1 + n];
        int row = (bRm + mg*4)*HDIM + bHn + n;
        g_h[row          ] = tanhf(fmaf(ts, wt, acc0 + bb));
        g_h[row +   HDIM ] = tanhf(fmaf(ts, wt, acc1 + bb));
        g_h[row + 2*HDIM ] = tanhf(fmaf(ts, wt, acc2 + bb));
        g_h[row + 3*HDIM ] = tanhf(fmaf(ts, wt, acc3 + bb));
      }
      gridbar();

      // ---- GEMM2: k_s = h @ W2 + b2, tile 32x16, 2-way K-split -----------
      {
        const int w = tid >> 5, lane = tid & 31;
        const int kz = w >> 3, nc = w & 7;       // kz: K half, nc: col pair
        float g0 = 0.f, g1 = 0.f;
        for (int c = 0; c < 4; c++) {
          int k0 = c*256;
          for (int i = tid; i < 32*256; i += NT) {  // stage h chunk [32][257]
            int m = i >> 8, kk = i & 255;
            sA[m*257 + kk] = g_h[(bRm + m)*HDIM + k0 + kk];
          }
          __syncthreads();
          const float* ap = &sA[lane*257 + kz*128];
          const float* bp = &sm[SM_W2 + (k0 + kz*128)*16 + nc*2];
          #pragma unroll 8
          for (int kk = 0; kk < 128; kk++) {
            float a = ap[kk];
            float2 bv = *(const float2*)(bp + kk*16);
            g0 = fmaf(a, bv.x, g0);
            g1 = fmaf(a, bv.y, g1);
          }
          __syncthreads();
        }
        // combine K halves + bias, re-stage for coalesced store
        if (kz == 1) {
          sA[(nc*2 + 0)*32 + lane] = g0;
          sA[(nc*2 + 1)*32 + lane] = g1;
        }
        __syncthreads();
        if (kz == 0) {
          float o0 = g0 + sA[(nc*2 + 0)*32 + lane] + sm[SM_B2 + nc*2 + 0];
          float o1 = g1 + sA[(nc*2 + 1)*32 + lane] + sm[SM_B2 + nc*2 + 1];
          sA[512 + lane*16 + nc*2 + 0] = o0;
          sA[512 + lane*16 + nc*2 + 1] = o1;
        }
        __syncthreads();
        { int m = tid >> 4, n2 = tid & 15;
          g_k[(kbase + s) & 7][(bRm + m)*FDIM + bKn + n2] = sA[512 + m*16 + n2]; }
      }
      gridbar();
    }

    // ---- x5, err, per-block partial (exactly 1 element/thread) ----------
    {
      float cb[7], cd[7];
      #pragma unroll
      for (int j = 0; j < 7; j++) { cb[j] = dt_c*c_B5[j]; cd[j] = dt_c*c_D[j]; }
      int i = b*NT + tid;
      float x = cur[i], x5 = x, err = 0.f;
      #pragma unroll
      for (int j = 0; j < 7; j++) {
        float kv = g_k[(kbase + j) & 7][i];
        x5  = fmaf(cb[j], kv, x5);
        err = fmaf(cd[j], kv, err);
      }
      nxt[i] = x5;
      float scale = fmaf(1e-3f, fmaxf(fabsf(x), fabsf(x5)), 1e-4f);
      float r = err / scale;
      sA[tid] = r*r;
      __syncthreads();
      #pragma unroll
      for (int st = 256; st > 0; st >>= 1) {
        if (tid < st) sA[tid] += sA[tid + st];
        __syncthreads();
      }
      if (tid == 0) g_part[b] = sA[0];
    }
    gridbar();

    // ---- finalize scalars (block 0) --------------------------------------
    if (b == 0) {
      sA[tid] = (tid < NB) ? g_part[tid] : 0.f;
      __syncthreads();
      #pragma unroll
      for (int st = 256; st > 0; st >>= 1) {
        if (tid < st) sA[tid] += sA[tid + st];
        __syncthreads();
      }
      if (tid == 0) {
        float err_norm = sqrtf(sA[0] * (1.0f/(float)NX));
        int accept = (err_norm <= 1.0f);
        float factor = 0.9f * powf(err_norm + 1e-10f, -0.2f);
        factor = fminf(fmaxf(factor, 0.2f), 5.0f);
        if (accept) {
          g_t = t + dt_c;
          g_par = par ^ 1;
          g_kbase = (kbase + 6) & 7;   // FSAL: new k0 slot = old k6 slot
          g_fsal = 1;
        } else {
          g_fsal = 0;
        }
        g_dt = dt_c * factor;
      }
    }
    gridbar();
  }

  // ---- write final trajectory row ----------------------------------------
  {
    int par = *(volatile int*)&g_par;
    int i = b*NT + tid;
    out[NX + i] = g_xbuf[par][i];
  }
}

extern "C" void kernel_launch(void* const* d_in, const int* in_sizes, int n_in,
                              void* d_out, int out_size) {
  const float* x0 = (const float*)d_in[0];
  const float* W1 = (const float*)d_in[1];
  const float* b1 = (const float*)d_in[2];
  const float* W2 = (const float*)d_in[3];
  const float* b2 = (const float*)d_in[4];
  float* out = (float*)d_out;

  cudaFuncSetAttribute(k_ode, cudaFuncAttributeMaxDynamicSharedMemorySize, SMEM_BYTES);
  k_init<<<NB, NT>>>(x0, out);
  k_ode<<<NB, NT, SMEM_BYTES>>>(W1, b1, W2, b2, out);
}